// round 13
// baseline (speedup 1.0000x reference)
#include <cuda_runtime.h>
#include <cuda_bf16.h>
#include <math.h>
#include <stdint.h>

// Problem constants
#define B    16
#define S    512
#define DIN  512
#define DH   1024
#define NG   4096           // 4 gates * DH, gate-interleaved: n' = col*4 + gate
#define ROWS (B*S)          // 8192
#define NBLK 128            // persistent grid size
#define TPB  512            // threads per persistent block (16 warps)
#define WREC_SZ (128*16*4*4*2*32)   // 2,097,152 u32 per array

// ---------------- device scratch (static, allocation-free) ----------------
__device__ float g_b0p[NG];       // packed biases (gate-interleaved)
__device__ float g_b1p[NG];
// recurrent weights pre-packed into per-thread mma B-fragment layout (bf16x2 per u32)
__device__ uint32_t g_wrh0[WREC_SZ], g_wrl0[WREC_SZ];
__device__ uint32_t g_wrh1[WREC_SZ], g_wrl1[WREC_SZ];
// xpre input weights, K-major [n'][k], hi/lo
__device__ __nv_bfloat16 g_wbh0[(size_t)NG*DIN], g_wbl0[(size_t)NG*DIN];
__device__ __nv_bfloat16 g_wbh1[(size_t)NG*DH],  g_wbl1[(size_t)NG*DH];
__device__ __nv_bfloat16 g_xh[(size_t)ROWS*DH];   // X hi ([row][k], stride = layer K)
__device__ __nv_bfloat16 g_xl[(size_t)ROWS*DH];   // X lo
__device__ float g_xpre[(size_t)ROWS*NG];   // precomputed input-gate contributions
__device__ float g_h1all[(size_t)ROWS*DH];  // layer1 H for all t (fc input)
// H state double-buffered, TRANSPOSED [k][b], bf16 hi/lo
__device__ __nv_bfloat16 g_hsbh[2][DH*B];
__device__ __nv_bfloat16 g_hsbl[2][DH*B];
// hierarchical barrier: 8 sub-counters (256B apart) + release flag
__device__ volatile unsigned g_barA[8 * 64];
__device__ volatile unsigned g_go;

struct WPtrs {
    const float* W0[4]; const float* b0[4];
    const float* W1[4]; const float* b1[4];
};

// ================= warp-MMA helpers (sm_80+ PTX, legal on base sm_103) =================
__device__ __forceinline__ uint32_t smem_u32(const void* p) {
    uint32_t a;
    asm("{ .reg .u64 t; cvta.to.shared.u64 t, %1; cvt.u32.u64 %0, t; }" : "=r"(a) : "l"(p));
    return a;
}
__device__ __forceinline__ void ldm_x4(uint32_t* r, uint32_t addr) {
    asm volatile("ldmatrix.sync.aligned.m8n8.x4.shared.b16 {%0,%1,%2,%3}, [%4];"
                 : "=r"(r[0]), "=r"(r[1]), "=r"(r[2]), "=r"(r[3]) : "r"(addr));
}
__device__ __forceinline__ void ldm_x4_t(uint32_t* r, uint32_t addr) {
    asm volatile("ldmatrix.sync.aligned.m8n8.x4.trans.shared.b16 {%0,%1,%2,%3}, [%4];"
                 : "=r"(r[0]), "=r"(r[1]), "=r"(r[2]), "=r"(r[3]) : "r"(addr));
}
__device__ __forceinline__ void mma_bf16(float* d, const uint32_t* a, const uint32_t* b) {
    asm volatile("mma.sync.aligned.m16n8k16.row.col.f32.bf16.bf16.f32 "
                 "{%0,%1,%2,%3}, {%4,%5,%6,%7}, {%8,%9}, {%0,%1,%2,%3};"
                 : "+f"(d[0]), "+f"(d[1]), "+f"(d[2]), "+f"(d[3])
                 : "r"(a[0]), "r"(a[1]), "r"(a[2]), "r"(a[3]), "r"(b[0]), "r"(b[1]));
}
static __device__ __forceinline__ uint32_t sw128(uint32_t x) { return x ^ ((x >> 3) & 0x70); }

// ---------------- bias packing ----------------
__global__ void packb_kernel(WPtrs p) {
    int np = blockIdx.x * blockDim.x + threadIdx.x;
    if (np >= NG) return;
    int col = np >> 2, g = np & 3;
    g_b0p[np] = p.b0[g][col];
    g_b1p[np] = p.b1[g][col];
}

// ---------------- recurrent weight pack: per-thread mma B-fragment layout ----------------
__global__ void packw_rec_kernel(WPtrs p, int layer) {
    int tid = blockIdx.x * blockDim.x + threadIdx.x;
    if (tid >= WREC_SZ) return;
    int lane = tid & 31;
    int r    = (tid >> 5) & 1;
    int nt   = (tid >> 6) & 3;
    int s    = (tid >> 8) & 3;
    int w    = (tid >> 10) & 15;
    int bx   = tid >> 14;
    int np  = bx * 32 + nt * 8 + (lane >> 2);
    int col = np >> 2, g = np & 3;
    int k   = w * 64 + s * 16 + r * 8 + (lane & 3) * 2;
    const float* W = layer ? p.W1[g] : p.W0[g];
    const int Koff = layer ? DH : DIN;
    float w0 = W[(size_t)(Koff + k) * DH + col];
    float w1 = W[(size_t)(Koff + k + 1) * DH + col];
    __nv_bfloat16 h0 = __float2bfloat16(w0), h1 = __float2bfloat16(w1);
    __nv_bfloat16 l0 = __float2bfloat16(w0 - __bfloat162float(h0));
    __nv_bfloat16 l1 = __float2bfloat16(w1 - __bfloat162float(h1));
    uint32_t hp = (uint32_t)__bfloat16_as_ushort(h0) | ((uint32_t)__bfloat16_as_ushort(h1) << 16);
    uint32_t lp = (uint32_t)__bfloat16_as_ushort(l0) | ((uint32_t)__bfloat16_as_ushort(l1) << 16);
    if (layer) { g_wrh1[tid] = hp; g_wrl1[tid] = lp; }
    else       { g_wrh0[tid] = hp; g_wrl0[tid] = lp; }
}

// ---------------- bf16 hi/lo pack of xpre input weights, K-major [n'][k] ----------------
__global__ void packw_bf16_kernel(WPtrs p, int layer) {
    const int K = layer ? DH : DIN;
    int tid = blockIdx.x * blockDim.x + threadIdx.x;
    if (tid >= NG * K) return;
    int np = tid / K, k = tid % K;
    int col = np >> 2, g = np & 3;
    float w = layer ? p.W1[g][k * DH + col] : p.W0[g][k * DH + col];
    __nv_bfloat16 hi = __float2bfloat16(w);
    __nv_bfloat16 lo = __float2bfloat16(w - __bfloat162float(hi));
    if (layer) { g_wbh1[tid] = hi; g_wbl1[tid] = lo; }
    else       { g_wbh0[tid] = hi; g_wbl0[tid] = lo; }
}

// ---------------- X hi/lo conversion (layer 0 only: emb gather, K=DIN) ----------------
__global__ void xcvt_kernel(const float* __restrict__ emb,
                            const int* __restrict__ tokens) {
    long long tid = (long long)blockIdx.x * blockDim.x + threadIdx.x;
    if (tid >= (long long)ROWS * DIN) return;
    int row = (int)(tid / DIN), k = (int)(tid % DIN);
    int b = row & 15, t = row >> 4;
    float v = emb[(size_t)tokens[b * S + t] * DIN + k];
    __nv_bfloat16 hi = __float2bfloat16(v);
    __nv_bfloat16 lo = __float2bfloat16(v - __bfloat162float(hi));
    g_xh[(size_t)row * DIN + k] = hi;
    g_xl[(size_t)row * DIN + k] = lo;
}

// ---------------- zero H state + barrier state ----------------
__global__ void init_kernel() {
    int tid = blockIdx.x * blockDim.x + threadIdx.x;
    if (tid < 16384)            ((uint32_t*)g_hsbh)[tid] = 0u;       // 2 bufs x 16384 bf16
    else if (tid < 32768)       ((uint32_t*)g_hsbl)[tid - 16384] = 0u;
    if (tid < 8 * 64) g_barA[tid] = 0u;
    if (tid == 0) g_go = 0u;
}

// ---------------- HMMA xpre GEMM: g_xpre = bias + X @ Wx (bf16 hi/lo x3) ----------------
__global__ void __launch_bounds__(256) mma_xpre_kernel(int layer) {
    __shared__ __align__(128) char sAraw[128 * 128];
    __shared__ __align__(128) char sBraw[64 * 128];

    const int K = layer ? DH : DIN;
    const __nv_bfloat16* Wh = layer ? g_wbh1 : g_wbh0;
    const __nv_bfloat16* Wl = layer ? g_wbl1 : g_wbl0;
    const float* biasp = layer ? g_b1p : g_b0p;

    const int tid  = threadIdx.x, wid = tid >> 5, lane = tid & 31;
    const int rbase = blockIdx.x * 128;
    const int nbase = blockIdx.y * 64;
    const int wm = wid >> 1, wn = wid & 1;

    const uint32_t sAb = smem_u32(sAraw), sBb = smem_u32(sBraw);

    const int ra0 = wm * 32 + (lane & 7) + (lane & 8);
    const int rb0 = wn * 32 + (lane & 7) + (((lane >> 4) & 1) * 8);
    const int ua  = (lane >> 4);
    const int ub  = ((lane >> 3) & 1);

    float acc[2][4][4];
    #pragma unroll
    for (int i = 0; i < 2; i++)
        #pragma unroll
        for (int j = 0; j < 4; j++)
            #pragma unroll
            for (int q = 0; q < 4; q++) acc[i][j][q] = 0.f;

    const int nch = K / 64;
    const int total = 3 * nch;

    uint4 xr[4], wr[2];
    {
        #pragma unroll
        for (int j = 0; j < 4; j++) {
            int gidx = j * 256 + tid, r = gidx >> 3, kg = gidx & 7;
            xr[j] = *(const uint4*)(g_xh + (size_t)(rbase + r) * K + kg * 8);
        }
        #pragma unroll
        for (int j = 0; j < 2; j++) {
            int gidx = j * 256 + tid, r = gidx >> 3, kg = gidx & 7;
            wr[j] = *(const uint4*)(Wh + (size_t)(nbase + r) * K + kg * 8);
        }
    }

    int p = 0, kc = 0;
    for (int it = 0; it < total; it++) {
        #pragma unroll
        for (int j = 0; j < 4; j++) {
            int gidx = j * 256 + tid, r = gidx >> 3, kg = gidx & 7;
            *(uint4*)(sAraw + sw128((uint32_t)(r * 128 + kg * 16))) = xr[j];
        }
        #pragma unroll
        for (int j = 0; j < 2; j++) {
            int gidx = j * 256 + tid, r = gidx >> 3, kg = gidx & 7;
            *(uint4*)(sBraw + sw128((uint32_t)(r * 128 + kg * 16))) = wr[j];
        }
        __syncthreads();

        int np2 = p, nkc = kc + 1;
        if (nkc == nch) { nkc = 0; np2 = p + 1; }
        if (it + 1 < total) {
            const __nv_bfloat16* Asrc = (np2 == 1) ? g_xl : g_xh;
            const __nv_bfloat16* Bsrc = (np2 == 2) ? Wl : Wh;
            const int koff = nkc * 64;
            #pragma unroll
            for (int j = 0; j < 4; j++) {
                int gidx = j * 256 + tid, r = gidx >> 3, kg = gidx & 7;
                xr[j] = *(const uint4*)(Asrc + (size_t)(rbase + r) * K + koff + kg * 8);
            }
            #pragma unroll
            for (int j = 0; j < 2; j++) {
                int gidx = j * 256 + tid, r = gidx >> 3, kg = gidx & 7;
                wr[j] = *(const uint4*)(Bsrc + (size_t)(nbase + r) * K + koff + kg * 8);
            }
        }

        #pragma unroll
        for (int s = 0; s < 4; s++) {
            uint32_t a0[4], a1[4], b0[4], b1[4];
            ldm_x4(a0, sAb + sw128((uint32_t)( ra0       * 128 + (s * 2 + ua) * 16)));
            ldm_x4(a1, sAb + sw128((uint32_t)((ra0 + 16) * 128 + (s * 2 + ua) * 16)));
            ldm_x4(b0, sBb + sw128((uint32_t)( rb0       * 128 + (s * 2 + ub) * 16)));
            ldm_x4(b1, sBb + sw128((uint32_t)((rb0 + 16) * 128 + (s * 2 + ub) * 16)));
            mma_bf16(acc[0][0], a0, b0 + 0);
            mma_bf16(acc[0][1], a0, b0 + 2);
            mma_bf16(acc[0][2], a0, b1 + 0);
            mma_bf16(acc[0][3], a0, b1 + 2);
            mma_bf16(acc[1][0], a1, b0 + 0);
            mma_bf16(acc[1][1], a1, b0 + 2);
            mma_bf16(acc[1][2], a1, b1 + 0);
            mma_bf16(acc[1][3], a1, b1 + 2);
        }
        __syncthreads();
        p = np2; kc = nkc;
    }

    #pragma unroll
    for (int mt = 0; mt < 2; mt++) {
        #pragma unroll
        for (int nt = 0; nt < 4; nt++) {
            int r = rbase + wm * 32 + mt * 16 + (lane >> 2);
            int c = nbase + wn * 32 + nt * 8 + (lane & 3) * 2;
            float bv0 = biasp[c], bv1 = biasp[c + 1];
            float2 o0 = make_float2(acc[mt][nt][0] + bv0, acc[mt][nt][1] + bv1);
            float2 o1 = make_float2(acc[mt][nt][2] + bv0, acc[mt][nt][3] + bv1);
            *(float2*)(g_xpre + (size_t)r * NG + c)       = o0;
            *(float2*)(g_xpre + (size_t)(r + 8) * NG + c) = o1;
        }
    }
}

// ---------------- persistent recurrent layer: HMMA + hierarchical barrier ----------------
// 128 blocks x 512 threads (16 warps). Block bx owns n' [bx*32,+32); warp w owns k-slice
// [w*64,+64). Per step: warp-private H stage (bf16 hi/lo), ldmatrix.trans, 48 mma,
// frag dump, 512-thread finalize (C in regs, fast-math, shfl gate gather).
// Barrier: arrivals spread over 8 sub-counters (256B apart, 16 arrivals each);
// block 0's warp 0 detects completion and publishes g_go; all others poll g_go only.
// Layer 0 finalize writes bf16 hi/lo straight into g_xh/g_xl (layer-1 GEMM input);
// layer 1 writes fp32 g_h1all for the fc head. Both overlap the barrier wait.
__global__ void __launch_bounds__(TPB) lstm_persist_kernel(int layer) {
    __shared__ __align__(16) char ssm[16 * 4096];   // 64KB: per-warp 4KB (stage A / frag dump)

    const uint32_t* Wh = layer ? g_wrh1 : g_wrh0;
    const uint32_t* Wl = layer ? g_wrl1 : g_wrl0;

    const int tid  = threadIdx.x;
    const int w    = tid >> 5, lane = tid & 31;
    const int bx   = blockIdx.x;
    const int col0 = bx * 8;
    // finalize mapping: b = w, nloc = lane (= cl*4 + g)
    const int fcl = lane >> 2, fg = lane & 3;

    // ---- preload B fragments (one-time): bh/bl[s][nt][r] ----
    uint32_t bh[4][4][2], bl[4][4][2];
    {
        int base = (bx * 16 + w) * 1024;
        #pragma unroll
        for (int s = 0; s < 4; s++)
            #pragma unroll
            for (int nt = 0; nt < 4; nt++)
                #pragma unroll
                for (int r = 0; r < 2; r++) {
                    int idx = base + s * 256 + nt * 64 + r * 32 + lane;
                    bh[s][nt][r] = Wh[idx];
                    bl[s][nt][r] = Wl[idx];
                }
    }

    const uint32_t sW  = smem_u32(ssm) + w * 4096;      // hi base; lo = +2048
    const uint32_t aoff = (uint32_t)(((lane & 7) + ((lane >> 4) << 3)) * 32 + ((lane >> 3) & 1) * 16);

    float Creg = 0.f;      // C state for (b=w, col0+fcl) — used by fg==0 threads

    for (int t = 0; t < S; t++) {
        const int cur = t & 1, nxt = cur ^ 1;

        // ---- prefetch xpre gate value (coalesced; hidden behind stage+mma) ----
        float xq = g_xpre[((size_t)t * B + w) * NG + bx * 32 + lane];

        // ---- stage this warp's H slice: 2KB hi + 2KB lo, warp-private ----
        {
            const uint4* srcH = (const uint4*)(g_hsbh[cur] + w * 1024);
            const uint4* srcL = (const uint4*)(g_hsbl[cur] + w * 1024);
            uint4* dH = (uint4*)(ssm + w * 4096);
            uint4* dL = (uint4*)(ssm + w * 4096 + 2048);
            #pragma unroll
            for (int j = 0; j < 4; j++) {
                dH[lane + j * 32] = __ldcg(srcH + lane + j * 32);
                dL[lane + j * 32] = __ldcg(srcL + lane + j * 32);
            }
        }
        __syncwarp();

        // ---- compute: 4 k16-steps x 4 n8-tiles x 3 passes ----
        float acc[4][4];
        #pragma unroll
        for (int nt = 0; nt < 4; nt++)
            #pragma unroll
            for (int q = 0; q < 4; q++) acc[nt][q] = 0.f;

        #pragma unroll
        for (int s = 0; s < 4; s++) {
            uint32_t ah[4], al[4];
            ldm_x4_t(ah, sW + s * 512 + aoff);
            ldm_x4_t(al, sW + 2048 + s * 512 + aoff);
            #pragma unroll
            for (int nt = 0; nt < 4; nt++) {
                mma_bf16(acc[nt], ah, bh[s][nt]);
                mma_bf16(acc[nt], al, bh[s][nt]);
                mma_bf16(acc[nt], ah, bl[s][nt]);
            }
        }
        __syncwarp();

        // ---- dump fragments into warp-private region (rb[b*36 + nloc]) ----
        {
            float* rb = (float*)(ssm + w * 4096);
            int m0 = lane >> 2, n0 = (lane & 3) * 2;
            #pragma unroll
            for (int nt = 0; nt < 4; nt++) {
                *(float2*)(rb + m0 * 36 + nt * 8 + n0)       = make_float2(acc[nt][0], acc[nt][1]);
                *(float2*)(rb + (m0 + 8) * 36 + nt * 8 + n0) = make_float2(acc[nt][2], acc[nt][3]);
            }
        }
        __syncthreads();

        // ---- reduce + finalize: ALL 512 threads, one per (b=w, nloc=lane) ----
        float v = xq;
        #pragma unroll
        for (int ww = 0; ww < 16; ww++)
            v += ((const float*)(ssm + ww * 4096))[w * 36 + lane];

        // unified activation: sigmoid for gates i/f/o, tanh for g
        float aC = (fg == 2) ? 2.f : 1.f;
        float bC = (fg == 2) ? -2.f : -1.f;
        float cC = (fg == 2) ? -1.f : 0.f;
        float act = __fdividef(aC, 1.f + __expf(bC * v)) + cC;

        int lb = lane & ~3;
        float aI = __shfl_sync(0xffffffffu, act, lb + 0);
        float aF = __shfl_sync(0xffffffffu, act, lb + 1);
        float aG = __shfl_sync(0xffffffffu, act, lb + 2);
        float aO = __shfl_sync(0xffffffffu, act, lb + 3);

        float Hval = 0.f;
        __nv_bfloat16 hHi, hLo;
        if (fg == 0) {
            float C = aF * Creg + aI * aG;
            Creg = C;
            float tC = __fdividef(2.f, 1.f + __expf(-2.f * C)) - 1.f;
            Hval = aO * tC;
            int col = col0 + fcl;
            hHi = __float2bfloat16(Hval);
            hLo = __float2bfloat16(Hval - __bfloat162float(hHi));
            g_hsbh[nxt][col * 16 + w] = hHi;
            g_hsbl[nxt][col * 16 + w] = hLo;
            __threadfence();
        }
        __syncthreads();

        // ---- arrive on this block's sub-counter ----
        if (tid == 0) {
            __threadfence();
            atomicAdd((unsigned*)&g_barA[(bx >> 4) * 64], 1u);
        }

        // ---- off-critical-path output stores (overlap the release wait) ----
        if (fg == 0) {
            size_t off = ((size_t)t * B + w) * DH + col0 + fcl;
            if (layer == 0) { g_xh[off] = hHi; g_xl[off] = hLo; }
            else            { g_h1all[off] = Hval; }
        }

        // ---- release / wait ----
        if (bx == 0) {
            if (w == 0) {
                unsigned target = (unsigned)(t + 1) * 16u;
                unsigned ok;
                do {
                    unsigned vC = target;
                    if (lane < 8) vC = g_barA[lane * 64];
                    ok = __all_sync(0xffffffffu, vC >= target);
                } while (!ok);
                if (lane == 0) { __threadfence(); g_go = (unsigned)(t + 1); }
            }
            __syncthreads();
        } else {
            if (tid == 0) {
                unsigned target = (unsigned)(t + 1);
                while (g_go < target) { __nanosleep(32); }
                __threadfence();
            }
            __syncthreads();
        }
    }
}

// ---------------- FC head + 2-class log_softmax ----------------
__global__ void __launch_bounds__(256) fc_kernel(const float* __restrict__ Wfc,
                                                 const float* __restrict__ bfc,
                                                 float* __restrict__ out) {
    int tid = threadIdx.x;
    int w = tid >> 5, lane = tid & 31;
    int row = blockIdx.x * 8 + w;
    const float* h = g_h1all + (size_t)row * DH;
    float a0 = 0.f, a1 = 0.f;
    for (int k = lane; k < DH; k += 32) {
        float hv = h[k];
        a0 += hv * Wfc[k * 2 + 0];
        a1 += hv * Wfc[k * 2 + 1];
    }
    #pragma unroll
    for (int off = 16; off; off >>= 1) {
        a0 += __shfl_xor_sync(0xFFFFFFFFu, a0, off);
        a1 += __shfl_xor_sync(0xFFFFFFFFu, a1, off);
    }
    if (lane == 0) {
        float l0 = a0 + bfc[0], l1 = a1 + bfc[1];
        float m  = fmaxf(l0, l1);
        float lse = m + logf(expf(l0 - m) + expf(l1 - m));
        int t = row >> 4, b = row & 15;
        out[((size_t)b * S + t) * 2 + 0] = l0 - lse;
        out[((size_t)b * S + t) * 2 + 1] = l1 - lse;
    }
}

// ---------------- launcher (graph-capturable, allocation-free) ----------------
extern "C" void kernel_launch(void* const* d_in, const int* in_sizes, int n_in,
                              void* d_out, int out_size) {
    const int*   tokens = (const int*)d_in[0];
    const float* emb    = (const float*)d_in[1];
    WPtrs p;
    for (int g = 0; g < 4; g++) {
        p.W0[g] = (const float*)d_in[2  + g * 2];
        p.b0[g] = (const float*)d_in[3  + g * 2];
        p.W1[g] = (const float*)d_in[10 + g * 2];
        p.b1[g] = (const float*)d_in[11 + g * 2];
    }
    const float* Wfc = (const float*)d_in[18];
    const float* bfc = (const float*)d_in[19];
    float* out = (float*)d_out;

    packb_kernel<<<(NG + 255) / 256, 256>>>(p);
    packw_rec_kernel<<<WREC_SZ / 256, 256>>>(p, 0);
    packw_rec_kernel<<<WREC_SZ / 256, 256>>>(p, 1);
    packw_bf16_kernel<<<(NG * DIN + 255) / 256, 256>>>(p, 0);
    packw_bf16_kernel<<<(NG * DH  + 255) / 256, 256>>>(p, 1);

    // ----- layer 0 -----
    init_kernel<<<128, 256>>>();
    xcvt_kernel<<<(ROWS * DIN + 255) / 256, 256>>>(emb, tokens);
    mma_xpre_kernel<<<dim3(ROWS / 128, NG / 64), 256>>>(0);
    lstm_persist_kernel<<<NBLK, TPB>>>(0);   // finalize writes g_xh/g_xl for layer 1

    // ----- layer 1 -----
    init_kernel<<<128, 256>>>();
    mma_xpre_kernel<<<dim3(ROWS / 128, NG / 64), 256>>>(1);
    lstm_persist_kernel<<<NBLK, TPB>>>(1);

    // ----- head -----
    fc_kernel<<<ROWS / 8, 256>>>(Wfc, bfc, out);
}

// round 14
// speedup vs baseline: 1.1215x; 1.1215x over previous
#include <cuda_runtime.h>
#include <cuda_bf16.h>
#include <math.h>
#include <stdint.h>

// Problem constants
#define B    16
#define S    512
#define DIN  512
#define DH   1024
#define NG   4096           // 4 gates * DH, gate-interleaved: n' = col*4 + gate
#define ROWS (B*S)          // 8192
#define NBLK 128            // persistent grid size
#define TPB  512            // threads per persistent block (16 warps)
#define WREC_SZ (128*16*4*4*2*32)   // 2,097,152 u32 per array

// ---------------- device scratch (static, allocation-free) ----------------
__device__ float g_b0p[NG];       // packed biases (gate-interleaved)
__device__ float g_b1p[NG];
// recurrent weights pre-packed into per-thread mma B-fragment layout (bf16x2 per u32)
__device__ uint32_t g_wrh0[WREC_SZ], g_wrl0[WREC_SZ];
__device__ uint32_t g_wrh1[WREC_SZ], g_wrl1[WREC_SZ];
// xpre input weights, K-major [n'][k], hi/lo
__device__ __nv_bfloat16 g_wbh0[(size_t)NG*DIN], g_wbl0[(size_t)NG*DIN];
__device__ __nv_bfloat16 g_wbh1[(size_t)NG*DH],  g_wbl1[(size_t)NG*DH];
__device__ __nv_bfloat16 g_xh[(size_t)ROWS*DH];   // X hi ([row][k], stride = layer K)
__device__ __nv_bfloat16 g_xl[(size_t)ROWS*DH];   // X lo
__device__ float g_xpre[(size_t)ROWS*NG];   // precomputed input-gate contributions
__device__ float g_h1all[(size_t)ROWS*DH];  // layer1 H for all t (fc input)
// H state double-buffered, TRANSPOSED [k][b], bf16 hi/lo
__device__ __nv_bfloat16 g_hsbh[2][DH*B];
__device__ __nv_bfloat16 g_hsbl[2][DH*B];
__device__ volatile unsigned g_bar;         // monotone grid-barrier counter (reset by init)

struct WPtrs {
    const float* W0[4]; const float* b0[4];
    const float* W1[4]; const float* b1[4];
};

// ================= warp-MMA helpers (sm_80+ PTX, legal on base sm_103) =================
__device__ __forceinline__ uint32_t smem_u32(const void* p) {
    uint32_t a;
    asm("{ .reg .u64 t; cvta.to.shared.u64 t, %1; cvt.u32.u64 %0, t; }" : "=r"(a) : "l"(p));
    return a;
}
__device__ __forceinline__ void ldm_x4(uint32_t* r, uint32_t addr) {
    asm volatile("ldmatrix.sync.aligned.m8n8.x4.shared.b16 {%0,%1,%2,%3}, [%4];"
                 : "=r"(r[0]), "=r"(r[1]), "=r"(r[2]), "=r"(r[3]) : "r"(addr));
}
__device__ __forceinline__ void ldm_x4_t(uint32_t* r, uint32_t addr) {
    asm volatile("ldmatrix.sync.aligned.m8n8.x4.trans.shared.b16 {%0,%1,%2,%3}, [%4];"
                 : "=r"(r[0]), "=r"(r[1]), "=r"(r[2]), "=r"(r[3]) : "r"(addr));
}
__device__ __forceinline__ void mma_bf16(float* d, const uint32_t* a, const uint32_t* b) {
    asm volatile("mma.sync.aligned.m16n8k16.row.col.f32.bf16.bf16.f32 "
                 "{%0,%1,%2,%3}, {%4,%5,%6,%7}, {%8,%9}, {%0,%1,%2,%3};"
                 : "+f"(d[0]), "+f"(d[1]), "+f"(d[2]), "+f"(d[3])
                 : "r"(a[0]), "r"(a[1]), "r"(a[2]), "r"(a[3]), "r"(b[0]), "r"(b[1]));
}
static __device__ __forceinline__ uint32_t sw128(uint32_t x) { return x ^ ((x >> 3) & 0x70); }

// ---------------- bias packing ----------------
__global__ void packb_kernel(WPtrs p) {
    int np = blockIdx.x * blockDim.x + threadIdx.x;
    if (np >= NG) return;
    int col = np >> 2, g = np & 3;
    g_b0p[np] = p.b0[g][col];
    g_b1p[np] = p.b1[g][col];
}

// ---------------- recurrent weight pack: per-thread mma B-fragment layout ----------------
__global__ void packw_rec_kernel(WPtrs p, int layer) {
    int tid = blockIdx.x * blockDim.x + threadIdx.x;
    if (tid >= WREC_SZ) return;
    int lane = tid & 31;
    int r    = (tid >> 5) & 1;
    int nt   = (tid >> 6) & 3;
    int s    = (tid >> 8) & 3;
    int w    = (tid >> 10) & 15;
    int bx   = tid >> 14;
    int np  = bx * 32 + nt * 8 + (lane >> 2);
    int col = np >> 2, g = np & 3;
    int k   = w * 64 + s * 16 + r * 8 + (lane & 3) * 2;
    const float* W = layer ? p.W1[g] : p.W0[g];
    const int Koff = layer ? DH : DIN;
    float w0 = W[(size_t)(Koff + k) * DH + col];
    float w1 = W[(size_t)(Koff + k + 1) * DH + col];
    __nv_bfloat16 h0 = __float2bfloat16(w0), h1 = __float2bfloat16(w1);
    __nv_bfloat16 l0 = __float2bfloat16(w0 - __bfloat162float(h0));
    __nv_bfloat16 l1 = __float2bfloat16(w1 - __bfloat162float(h1));
    uint32_t hp = (uint32_t)__bfloat16_as_ushort(h0) | ((uint32_t)__bfloat16_as_ushort(h1) << 16);
    uint32_t lp = (uint32_t)__bfloat16_as_ushort(l0) | ((uint32_t)__bfloat16_as_ushort(l1) << 16);
    if (layer) { g_wrh1[tid] = hp; g_wrl1[tid] = lp; }
    else       { g_wrh0[tid] = hp; g_wrl0[tid] = lp; }
}

// ---------------- bf16 hi/lo pack of xpre input weights, K-major [n'][k] ----------------
__global__ void packw_bf16_kernel(WPtrs p, int layer) {
    const int K = layer ? DH : DIN;
    int tid = blockIdx.x * blockDim.x + threadIdx.x;
    if (tid >= NG * K) return;
    int np = tid / K, k = tid % K;
    int col = np >> 2, g = np & 3;
    float w = layer ? p.W1[g][k * DH + col] : p.W0[g][k * DH + col];
    __nv_bfloat16 hi = __float2bfloat16(w);
    __nv_bfloat16 lo = __float2bfloat16(w - __bfloat162float(hi));
    if (layer) { g_wbh1[tid] = hi; g_wbl1[tid] = lo; }
    else       { g_wbh0[tid] = hi; g_wbl0[tid] = lo; }
}

// ---------------- X hi/lo conversion (layer 0 only: emb gather, K=DIN) ----------------
__global__ void xcvt_kernel(const float* __restrict__ emb,
                            const int* __restrict__ tokens) {
    long long tid = (long long)blockIdx.x * blockDim.x + threadIdx.x;
    if (tid >= (long long)ROWS * DIN) return;
    int row = (int)(tid / DIN), k = (int)(tid % DIN);
    int b = row & 15, t = row >> 4;
    float v = emb[(size_t)tokens[b * S + t] * DIN + k];
    __nv_bfloat16 hi = __float2bfloat16(v);
    __nv_bfloat16 lo = __float2bfloat16(v - __bfloat162float(hi));
    g_xh[(size_t)row * DIN + k] = hi;
    g_xl[(size_t)row * DIN + k] = lo;
}

// ---------------- zero H state + barrier counter ----------------
__global__ void init_kernel() {
    int tid = blockIdx.x * blockDim.x + threadIdx.x;
    if (tid < 16384)            ((uint32_t*)g_hsbh)[tid] = 0u;       // 2 bufs x 16384 bf16
    else if (tid < 32768)       ((uint32_t*)g_hsbl)[tid - 16384] = 0u;
    if (tid == 0) g_bar = 0u;
}

// ---------------- HMMA xpre GEMM: g_xpre = bias + X @ Wx (bf16 hi/lo x3) ----------------
__global__ void __launch_bounds__(256) mma_xpre_kernel(int layer) {
    __shared__ __align__(128) char sAraw[128 * 128];
    __shared__ __align__(128) char sBraw[64 * 128];

    const int K = layer ? DH : DIN;
    const __nv_bfloat16* Wh = layer ? g_wbh1 : g_wbh0;
    const __nv_bfloat16* Wl = layer ? g_wbl1 : g_wbl0;
    const float* biasp = layer ? g_b1p : g_b0p;

    const int tid  = threadIdx.x, wid = tid >> 5, lane = tid & 31;
    const int rbase = blockIdx.x * 128;
    const int nbase = blockIdx.y * 64;
    const int wm = wid >> 1, wn = wid & 1;

    const uint32_t sAb = smem_u32(sAraw), sBb = smem_u32(sBraw);

    const int ra0 = wm * 32 + (lane & 7) + (lane & 8);
    const int rb0 = wn * 32 + (lane & 7) + (((lane >> 4) & 1) * 8);
    const int ua  = (lane >> 4);
    const int ub  = ((lane >> 3) & 1);

    float acc[2][4][4];
    #pragma unroll
    for (int i = 0; i < 2; i++)
        #pragma unroll
        for (int j = 0; j < 4; j++)
            #pragma unroll
            for (int q = 0; q < 4; q++) acc[i][j][q] = 0.f;

    const int nch = K / 64;
    const int total = 3 * nch;

    uint4 xr[4], wr[2];
    {
        #pragma unroll
        for (int j = 0; j < 4; j++) {
            int gidx = j * 256 + tid, r = gidx >> 3, kg = gidx & 7;
            xr[j] = *(const uint4*)(g_xh + (size_t)(rbase + r) * K + kg * 8);
        }
        #pragma unroll
        for (int j = 0; j < 2; j++) {
            int gidx = j * 256 + tid, r = gidx >> 3, kg = gidx & 7;
            wr[j] = *(const uint4*)(Wh + (size_t)(nbase + r) * K + kg * 8);
        }
    }

    int p = 0, kc = 0;
    for (int it = 0; it < total; it++) {
        #pragma unroll
        for (int j = 0; j < 4; j++) {
            int gidx = j * 256 + tid, r = gidx >> 3, kg = gidx & 7;
            *(uint4*)(sAraw + sw128((uint32_t)(r * 128 + kg * 16))) = xr[j];
        }
        #pragma unroll
        for (int j = 0; j < 2; j++) {
            int gidx = j * 256 + tid, r = gidx >> 3, kg = gidx & 7;
            *(uint4*)(sBraw + sw128((uint32_t)(r * 128 + kg * 16))) = wr[j];
        }
        __syncthreads();

        int np2 = p, nkc = kc + 1;
        if (nkc == nch) { nkc = 0; np2 = p + 1; }
        if (it + 1 < total) {
            const __nv_bfloat16* Asrc = (np2 == 1) ? g_xl : g_xh;
            const __nv_bfloat16* Bsrc = (np2 == 2) ? Wl : Wh;
            const int koff = nkc * 64;
            #pragma unroll
            for (int j = 0; j < 4; j++) {
                int gidx = j * 256 + tid, r = gidx >> 3, kg = gidx & 7;
                xr[j] = *(const uint4*)(Asrc + (size_t)(rbase + r) * K + koff + kg * 8);
            }
            #pragma unroll
            for (int j = 0; j < 2; j++) {
                int gidx = j * 256 + tid, r = gidx >> 3, kg = gidx & 7;
                wr[j] = *(const uint4*)(Bsrc + (size_t)(nbase + r) * K + koff + kg * 8);
            }
        }

        #pragma unroll
        for (int s = 0; s < 4; s++) {
            uint32_t a0[4], a1[4], b0[4], b1[4];
            ldm_x4(a0, sAb + sw128((uint32_t)( ra0       * 128 + (s * 2 + ua) * 16)));
            ldm_x4(a1, sAb + sw128((uint32_t)((ra0 + 16) * 128 + (s * 2 + ua) * 16)));
            ldm_x4(b0, sBb + sw128((uint32_t)( rb0       * 128 + (s * 2 + ub) * 16)));
            ldm_x4(b1, sBb + sw128((uint32_t)((rb0 + 16) * 128 + (s * 2 + ub) * 16)));
            mma_bf16(acc[0][0], a0, b0 + 0);
            mma_bf16(acc[0][1], a0, b0 + 2);
            mma_bf16(acc[0][2], a0, b1 + 0);
            mma_bf16(acc[0][3], a0, b1 + 2);
            mma_bf16(acc[1][0], a1, b0 + 0);
            mma_bf16(acc[1][1], a1, b0 + 2);
            mma_bf16(acc[1][2], a1, b1 + 0);
            mma_bf16(acc[1][3], a1, b1 + 2);
        }
        __syncthreads();
        p = np2; kc = nkc;
    }

    #pragma unroll
    for (int mt = 0; mt < 2; mt++) {
        #pragma unroll
        for (int nt = 0; nt < 4; nt++) {
            int r = rbase + wm * 32 + mt * 16 + (lane >> 2);
            int c = nbase + wn * 32 + nt * 8 + (lane & 3) * 2;
            float bv0 = biasp[c], bv1 = biasp[c + 1];
            float2 o0 = make_float2(acc[mt][nt][0] + bv0, acc[mt][nt][1] + bv1);
            float2 o1 = make_float2(acc[mt][nt][2] + bv0, acc[mt][nt][3] + bv1);
            *(float2*)(g_xpre + (size_t)r * NG + c)       = o0;
            *(float2*)(g_xpre + (size_t)(r + 8) * NG + c) = o1;
        }
    }
}

// ---------------- persistent recurrent layer: HMMA + flat central barrier ----------------
// 128 blocks x 512 threads (16 warps). Block bx owns n' [bx*32,+32); warp w owns k-slice
// [w*64,+64). B fragments (hi/lo) in 64 regs/thread, loaded once. Per step: warp-private
// H stage (bf16 hi/lo), ldmatrix.trans, 48 mma, frag dump, 512-thread finalize (C in regs,
// fast-math, shfl gate gather). ONE flat monotone barrier (single counter; one poller per
// block). Layer-0 finalize writes bf16 hi/lo directly into g_xh/g_xl (layer-1 GEMM input);
// layer-1 writes fp32 g_h1all for fc. Output stores overlap the barrier poll.
__global__ void __launch_bounds__(TPB) lstm_persist_kernel(int layer) {
    __shared__ __align__(16) char ssm[16 * 4096];   // 64KB: per-warp 4KB (stage A / frag dump)

    const uint32_t* Wh = layer ? g_wrh1 : g_wrh0;
    const uint32_t* Wl = layer ? g_wrl1 : g_wrl0;

    const int tid  = threadIdx.x;
    const int w    = tid >> 5, lane = tid & 31;
    const int bx   = blockIdx.x;
    const int col0 = bx * 8;
    // finalize mapping: b = w, nloc = lane (= cl*4 + g)
    const int fcl = lane >> 2, fg = lane & 3;

    // ---- preload B fragments (one-time): bh/bl[s][nt][r] ----
    uint32_t bh[4][4][2], bl[4][4][2];
    {
        int base = (bx * 16 + w) * 1024;
        #pragma unroll
        for (int s = 0; s < 4; s++)
            #pragma unroll
            for (int nt = 0; nt < 4; nt++)
                #pragma unroll
                for (int r = 0; r < 2; r++) {
                    int idx = base + s * 256 + nt * 64 + r * 32 + lane;
                    bh[s][nt][r] = Wh[idx];
                    bl[s][nt][r] = Wl[idx];
                }
    }

    const uint32_t sW  = smem_u32(ssm) + w * 4096;      // hi base; lo = +2048
    const uint32_t aoff = (uint32_t)(((lane & 7) + ((lane >> 4) << 3)) * 32 + ((lane >> 3) & 1) * 16);

    float Creg = 0.f;      // C state for (b=w, col0+fcl) — used by fg==0 threads

    for (int t = 0; t < S; t++) {
        const int cur = t & 1, nxt = cur ^ 1;

        // ---- prefetch xpre gate value (coalesced; hidden behind stage+mma) ----
        float xq = g_xpre[((size_t)t * B + w) * NG + bx * 32 + lane];

        // ---- stage this warp's H slice: 2KB hi + 2KB lo, warp-private ----
        {
            const uint4* srcH = (const uint4*)(g_hsbh[cur] + w * 1024);
            const uint4* srcL = (const uint4*)(g_hsbl[cur] + w * 1024);
            uint4* dH = (uint4*)(ssm + w * 4096);
            uint4* dL = (uint4*)(ssm + w * 4096 + 2048);
            #pragma unroll
            for (int j = 0; j < 4; j++) {
                dH[lane + j * 32] = __ldcg(srcH + lane + j * 32);
                dL[lane + j * 32] = __ldcg(srcL + lane + j * 32);
            }
        }
        __syncwarp();

        // ---- compute: 4 k16-steps x 4 n8-tiles x 3 passes ----
        float acc[4][4];
        #pragma unroll
        for (int nt = 0; nt < 4; nt++)
            #pragma unroll
            for (int q = 0; q < 4; q++) acc[nt][q] = 0.f;

        #pragma unroll
        for (int s = 0; s < 4; s++) {
            uint32_t ah[4], al[4];
            ldm_x4_t(ah, sW + s * 512 + aoff);
            ldm_x4_t(al, sW + 2048 + s * 512 + aoff);
            #pragma unroll
            for (int nt = 0; nt < 4; nt++) {
                mma_bf16(acc[nt], ah, bh[s][nt]);
                mma_bf16(acc[nt], al, bh[s][nt]);
                mma_bf16(acc[nt], ah, bl[s][nt]);
            }
        }
        __syncwarp();

        // ---- dump fragments into warp-private region (rb[b*36 + nloc]) ----
        {
            float* rb = (float*)(ssm + w * 4096);
            int m0 = lane >> 2, n0 = (lane & 3) * 2;
            #pragma unroll
            for (int nt = 0; nt < 4; nt++) {
                *(float2*)(rb + m0 * 36 + nt * 8 + n0)       = make_float2(acc[nt][0], acc[nt][1]);
                *(float2*)(rb + (m0 + 8) * 36 + nt * 8 + n0) = make_float2(acc[nt][2], acc[nt][3]);
            }
        }
        __syncthreads();

        // ---- reduce + finalize: ALL 512 threads, one per (b=w, nloc=lane) ----
        float v = xq;
        #pragma unroll
        for (int ww = 0; ww < 16; ww++)
            v += ((const float*)(ssm + ww * 4096))[w * 36 + lane];

        // unified activation: sigmoid for gates i/f/o, tanh for g
        float aC = (fg == 2) ? 2.f : 1.f;
        float bC = (fg == 2) ? -2.f : -1.f;
        float cC = (fg == 2) ? -1.f : 0.f;
        float act = __fdividef(aC, 1.f + __expf(bC * v)) + cC;

        int lb = lane & ~3;
        float aI = __shfl_sync(0xffffffffu, act, lb + 0);
        float aF = __shfl_sync(0xffffffffu, act, lb + 1);
        float aG = __shfl_sync(0xffffffffu, act, lb + 2);
        float aO = __shfl_sync(0xffffffffu, act, lb + 3);

        float Hval = 0.f;
        __nv_bfloat16 hHi, hLo;
        if (fg == 0) {
            float C = aF * Creg + aI * aG;
            Creg = C;
            float tC = __fdividef(2.f, 1.f + __expf(-2.f * C)) - 1.f;
            Hval = aO * tC;
            int col = col0 + fcl;
            hHi = __float2bfloat16(Hval);
            hLo = __float2bfloat16(Hval - __bfloat162float(hHi));
            g_hsbh[nxt][col * 16 + w] = hHi;
            g_hsbl[nxt][col * 16 + w] = hLo;
            __threadfence();
        }
        __syncthreads();

        // ---- flat central barrier; output stores overlap the poll ----
        if (tid == 0) {
            __threadfence();
            atomicAdd((unsigned*)&g_bar, 1u);
        }
        if (fg == 0) {
            size_t off = ((size_t)t * B + w) * DH + col0 + fcl;
            if (layer == 0) { g_xh[off] = hHi; g_xl[off] = hLo; }
            else            { g_h1all[off] = Hval; }
        }
        if (tid == 0) {
            unsigned target = (unsigned)(t + 1) * NBLK;
            while (g_bar < target) { __nanosleep(32); }
            __threadfence();
        }
        __syncthreads();
    }
}

// ---------------- FC head + 2-class log_softmax ----------------
__global__ void __launch_bounds__(256) fc_kernel(const float* __restrict__ Wfc,
                                                 const float* __restrict__ bfc,
                                                 float* __restrict__ out) {
    int tid = threadIdx.x;
    int w = tid >> 5, lane = tid & 31;
    int row = blockIdx.x * 8 + w;
    const float* h = g_h1all + (size_t)row * DH;
    float a0 = 0.f, a1 = 0.f;
    for (int k = lane; k < DH; k += 32) {
        float hv = h[k];
        a0 += hv * Wfc[k * 2 + 0];
        a1 += hv * Wfc[k * 2 + 1];
    }
    #pragma unroll
    for (int off = 16; off; off >>= 1) {
        a0 += __shfl_xor_sync(0xFFFFFFFFu, a0, off);
        a1 += __shfl_xor_sync(0xFFFFFFFFu, a1, off);
    }
    if (lane == 0) {
        float l0 = a0 + bfc[0], l1 = a1 + bfc[1];
        float m  = fmaxf(l0, l1);
        float lse = m + logf(expf(l0 - m) + expf(l1 - m));
        int t = row >> 4, b = row & 15;
        out[((size_t)b * S + t) * 2 + 0] = l0 - lse;
        out[((size_t)b * S + t) * 2 + 1] = l1 - lse;
    }
}

// ---------------- launcher (graph-capturable, allocation-free) ----------------
extern "C" void kernel_launch(void* const* d_in, const int* in_sizes, int n_in,
                              void* d_out, int out_size) {
    const int*   tokens = (const int*)d_in[0];
    const float* emb    = (const float*)d_in[1];
    WPtrs p;
    for (int g = 0; g < 4; g++) {
        p.W0[g] = (const float*)d_in[2  + g * 2];
        p.b0[g] = (const float*)d_in[3  + g * 2];
        p.W1[g] = (const float*)d_in[10 + g * 2];
        p.b1[g] = (const float*)d_in[11 + g * 2];
    }
    const float* Wfc = (const float*)d_in[18];
    const float* bfc = (const float*)d_in[19];
    float* out = (float*)d_out;

    packb_kernel<<<(NG + 255) / 256, 256>>>(p);
    packw_rec_kernel<<<WREC_SZ / 256, 256>>>(p, 0);
    packw_rec_kernel<<<WREC_SZ / 256, 256>>>(p, 1);
    packw_bf16_kernel<<<(NG * DIN + 255) / 256, 256>>>(p, 0);
    packw_bf16_kernel<<<(NG * DH  + 255) / 256, 256>>>(p, 1);

    // ----- layer 0 -----
    init_kernel<<<128, 256>>>();
    xcvt_kernel<<<(ROWS * DIN + 255) / 256, 256>>>(emb, tokens);
    mma_xpre_kernel<<<dim3(ROWS / 128, NG / 64), 256>>>(0);
    lstm_persist_kernel<<<NBLK, TPB>>>(0);   // finalize writes g_xh/g_xl for layer 1

    // ----- layer 1 -----
    init_kernel<<<128, 256>>>();
    mma_xpre_kernel<<<dim3(ROWS / 128, NG / 64), 256>>>(1);
    lstm_persist_kernel<<<NBLK, TPB>>>(1);

    // ----- head -----
    fc_kernel<<<ROWS / 8, 256>>>(Wfc, bfc, out);
}

// round 16
// speedup vs baseline: 1.3416x; 1.1962x over previous
#include <cuda_runtime.h>
#include <cuda_bf16.h>
#include <math.h>
#include <stdint.h>

// Problem constants
#define B    16
#define S    512
#define DIN  512
#define DH   1024
#define NG   4096           // 4 gates * DH, gate-interleaved: n' = col*4 + gate
#define ROWS (B*S)          // 8192
#define NBLK 128            // persistent grid size
#define TPB  512            // threads per persistent block (16 warps)
#define WREC_SZ (128*16*4*4*2*32)   // 2,097,152 u32 per array

// ---------------- device scratch (static, allocation-free) ----------------
__device__ float g_b0p[NG];       // packed biases (gate-interleaved)
__device__ float g_b1p[NG];
// recurrent weights pre-packed into per-thread mma B-fragment layout (bf16x2 per u32)
__device__ uint32_t g_wrh0[WREC_SZ], g_wrl0[WREC_SZ];
__device__ uint32_t g_wrh1[WREC_SZ], g_wrl1[WREC_SZ];
// xpre input weights, K-major [n'][k], hi/lo
__device__ __nv_bfloat16 g_wbh0[(size_t)NG*DIN], g_wbl0[(size_t)NG*DIN];
__device__ __nv_bfloat16 g_wbh1[(size_t)NG*DH],  g_wbl1[(size_t)NG*DH];
__device__ __nv_bfloat16 g_xh[(size_t)ROWS*DH];   // X hi ([row][k], stride = layer K)
__device__ __nv_bfloat16 g_xl[(size_t)ROWS*DH];   // X lo
__device__ float g_xpre[(size_t)ROWS*NG];   // precomputed input-gate contributions
__device__ float g_h1all[(size_t)ROWS*DH];  // layer1 H for all t (fc input)
// H state double-buffered, TRANSPOSED [k][b], bf16 hi/lo
__device__ __nv_bfloat16 g_hsbh[2][DH*B];
__device__ __nv_bfloat16 g_hsbl[2][DH*B];
__device__ unsigned g_bar;                  // monotone grid-barrier counter (reset by init)

struct WPtrs {
    const float* W0[4]; const float* b0[4];
    const float* W1[4]; const float* b1[4];
};

// ================= warp-MMA + sync helpers (sm_80+ PTX, legal on base sm_103) =================
__device__ __forceinline__ uint32_t smem_u32(const void* p) {
    uint32_t a;
    asm("{ .reg .u64 t; cvta.to.shared.u64 t, %1; cvt.u32.u64 %0, t; }" : "=r"(a) : "l"(p));
    return a;
}
__device__ __forceinline__ void ldm_x4(uint32_t* r, uint32_t addr) {
    asm volatile("ldmatrix.sync.aligned.m8n8.x4.shared.b16 {%0,%1,%2,%3}, [%4];"
                 : "=r"(r[0]), "=r"(r[1]), "=r"(r[2]), "=r"(r[3]) : "r"(addr));
}
__device__ __forceinline__ void ldm_x4_t(uint32_t* r, uint32_t addr) {
    asm volatile("ldmatrix.sync.aligned.m8n8.x4.trans.shared.b16 {%0,%1,%2,%3}, [%4];"
                 : "=r"(r[0]), "=r"(r[1]), "=r"(r[2]), "=r"(r[3]) : "r"(addr));
}
__device__ __forceinline__ void mma_bf16(float* d, const uint32_t* a, const uint32_t* b) {
    asm volatile("mma.sync.aligned.m16n8k16.row.col.f32.bf16.bf16.f32 "
                 "{%0,%1,%2,%3}, {%4,%5,%6,%7}, {%8,%9}, {%0,%1,%2,%3};"
                 : "+f"(d[0]), "+f"(d[1]), "+f"(d[2]), "+f"(d[3])
                 : "r"(a[0]), "r"(a[1]), "r"(a[2]), "r"(a[3]), "r"(b[0]), "r"(b[1]));
}
static __device__ __forceinline__ uint32_t sw128(uint32_t x) { return x ^ ((x >> 3) & 0x70); }
// release-scoped arrive: cumulative release publishes all block stores ordered by the
// preceding __syncthreads (no explicit MEMBAR.GPU needed)
__device__ __forceinline__ void red_release_add(unsigned* addr, unsigned v) {
    asm volatile("red.release.gpu.global.add.u32 [%0], %1;" :: "l"(addr), "r"(v) : "memory");
}
__device__ __forceinline__ unsigned ld_acquire_gpu(const unsigned* addr) {
    unsigned v;
    asm volatile("ld.acquire.gpu.global.u32 %0, [%1];" : "=r"(v) : "l"(addr) : "memory");
    return v;
}

// ---------------- bias packing ----------------
__global__ void packb_kernel(WPtrs p) {
    int np = blockIdx.x * blockDim.x + threadIdx.x;
    if (np >= NG) return;
    int col = np >> 2, g = np & 3;
    g_b0p[np] = p.b0[g][col];
    g_b1p[np] = p.b1[g][col];
}

// ---------------- recurrent weight pack: per-thread mma B-fragment layout ----------------
__global__ void packw_rec_kernel(WPtrs p, int layer) {
    int tid = blockIdx.x * blockDim.x + threadIdx.x;
    if (tid >= WREC_SZ) return;
    int lane = tid & 31;
    int r    = (tid >> 5) & 1;
    int nt   = (tid >> 6) & 3;
    int s    = (tid >> 8) & 3;
    int w    = (tid >> 10) & 15;
    int bx   = tid >> 14;
    int np  = bx * 32 + nt * 8 + (lane >> 2);
    int col = np >> 2, g = np & 3;
    int k   = w * 64 + s * 16 + r * 8 + (lane & 3) * 2;
    const float* W = layer ? p.W1[g] : p.W0[g];
    const int Koff = layer ? DH : DIN;
    float w0 = W[(size_t)(Koff + k) * DH + col];
    float w1 = W[(size_t)(Koff + k + 1) * DH + col];
    __nv_bfloat16 h0 = __float2bfloat16(w0), h1 = __float2bfloat16(w1);
    __nv_bfloat16 l0 = __float2bfloat16(w0 - __bfloat162float(h0));
    __nv_bfloat16 l1 = __float2bfloat16(w1 - __bfloat162float(h1));
    uint32_t hp = (uint32_t)__bfloat16_as_ushort(h0) | ((uint32_t)__bfloat16_as_ushort(h1) << 16);
    uint32_t lp = (uint32_t)__bfloat16_as_ushort(l0) | ((uint32_t)__bfloat16_as_ushort(l1) << 16);
    if (layer) { g_wrh1[tid] = hp; g_wrl1[tid] = lp; }
    else       { g_wrh0[tid] = hp; g_wrl0[tid] = lp; }
}

// ---------------- bf16 hi/lo pack of xpre input weights, K-major [n'][k] ----------------
__global__ void packw_bf16_kernel(WPtrs p, int layer) {
    const int K = layer ? DH : DIN;
    int tid = blockIdx.x * blockDim.x + threadIdx.x;
    if (tid >= NG * K) return;
    int np = tid / K, k = tid % K;
    int col = np >> 2, g = np & 3;
    float w = layer ? p.W1[g][k * DH + col] : p.W0[g][k * DH + col];
    __nv_bfloat16 hi = __float2bfloat16(w);
    __nv_bfloat16 lo = __float2bfloat16(w - __bfloat162float(hi));
    if (layer) { g_wbh1[tid] = hi; g_wbl1[tid] = lo; }
    else       { g_wbh0[tid] = hi; g_wbl0[tid] = lo; }
}

// ---------------- X hi/lo conversion (layer 0 only: emb gather, K=DIN) ----------------
__global__ void xcvt_kernel(const float* __restrict__ emb,
                            const int* __restrict__ tokens) {
    long long tid = (long long)blockIdx.x * blockDim.x + threadIdx.x;
    if (tid >= (long long)ROWS * DIN) return;
    int row = (int)(tid / DIN), k = (int)(tid % DIN);
    int b = row & 15, t = row >> 4;
    float v = emb[(size_t)tokens[b * S + t] * DIN + k];
    __nv_bfloat16 hi = __float2bfloat16(v);
    __nv_bfloat16 lo = __float2bfloat16(v - __bfloat162float(hi));
    g_xh[(size_t)row * DIN + k] = hi;
    g_xl[(size_t)row * DIN + k] = lo;
}

// ---------------- zero H state + barrier counter ----------------
__global__ void init_kernel() {
    int tid = blockIdx.x * blockDim.x + threadIdx.x;
    if (tid < 16384)            ((uint32_t*)g_hsbh)[tid] = 0u;       // 2 bufs x 16384 bf16
    else if (tid < 32768)       ((uint32_t*)g_hsbl)[tid - 16384] = 0u;
    if (tid == 0) g_bar = 0u;
}

// ---------------- HMMA xpre GEMM: g_xpre = bias + X @ Wx (bf16 hi/lo x3) ----------------
__global__ void __launch_bounds__(256) mma_xpre_kernel(int layer) {
    __shared__ __align__(128) char sAraw[128 * 128];
    __shared__ __align__(128) char sBraw[64 * 128];

    const int K = layer ? DH : DIN;
    const __nv_bfloat16* Wh = layer ? g_wbh1 : g_wbh0;
    const __nv_bfloat16* Wl = layer ? g_wbl1 : g_wbl0;
    const float* biasp = layer ? g_b1p : g_b0p;

    const int tid  = threadIdx.x, wid = tid >> 5, lane = tid & 31;
    const int rbase = blockIdx.x * 128;
    const int nbase = blockIdx.y * 64;
    const int wm = wid >> 1, wn = wid & 1;

    const uint32_t sAb = smem_u32(sAraw), sBb = smem_u32(sBraw);

    const int ra0 = wm * 32 + (lane & 7) + (lane & 8);
    const int rb0 = wn * 32 + (lane & 7) + (((lane >> 4) & 1) * 8);
    const int ua  = (lane >> 4);
    const int ub  = ((lane >> 3) & 1);

    float acc[2][4][4];
    #pragma unroll
    for (int i = 0; i < 2; i++)
        #pragma unroll
        for (int j = 0; j < 4; j++)
            #pragma unroll
            for (int q = 0; q < 4; q++) acc[i][j][q] = 0.f;

    const int nch = K / 64;
    const int total = 3 * nch;

    uint4 xr[4], wr[2];
    {
        #pragma unroll
        for (int j = 0; j < 4; j++) {
            int gidx = j * 256 + tid, r = gidx >> 3, kg = gidx & 7;
            xr[j] = *(const uint4*)(g_xh + (size_t)(rbase + r) * K + kg * 8);
        }
        #pragma unroll
        for (int j = 0; j < 2; j++) {
            int gidx = j * 256 + tid, r = gidx >> 3, kg = gidx & 7;
            wr[j] = *(const uint4*)(Wh + (size_t)(nbase + r) * K + kg * 8);
        }
    }

    int p = 0, kc = 0;
    for (int it = 0; it < total; it++) {
        #pragma unroll
        for (int j = 0; j < 4; j++) {
            int gidx = j * 256 + tid, r = gidx >> 3, kg = gidx & 7;
            *(uint4*)(sAraw + sw128((uint32_t)(r * 128 + kg * 16))) = xr[j];
        }
        #pragma unroll
        for (int j = 0; j < 2; j++) {
            int gidx = j * 256 + tid, r = gidx >> 3, kg = gidx & 7;
            *(uint4*)(sBraw + sw128((uint32_t)(r * 128 + kg * 16))) = wr[j];
        }
        __syncthreads();

        int np2 = p, nkc = kc + 1;
        if (nkc == nch) { nkc = 0; np2 = p + 1; }
        if (it + 1 < total) {
            const __nv_bfloat16* Asrc = (np2 == 1) ? g_xl : g_xh;
            const __nv_bfloat16* Bsrc = (np2 == 2) ? Wl : Wh;
            const int koff = nkc * 64;
            #pragma unroll
            for (int j = 0; j < 4; j++) {
                int gidx = j * 256 + tid, r = gidx >> 3, kg = gidx & 7;
                xr[j] = *(const uint4*)(Asrc + (size_t)(rbase + r) * K + koff + kg * 8);
            }
            #pragma unroll
            for (int j = 0; j < 2; j++) {
                int gidx = j * 256 + tid, r = gidx >> 3, kg = gidx & 7;
                wr[j] = *(const uint4*)(Bsrc + (size_t)(nbase + r) * K + koff + kg * 8);
            }
        }

        #pragma unroll
        for (int s = 0; s < 4; s++) {
            uint32_t a0[4], a1[4], b0[4], b1[4];
            ldm_x4(a0, sAb + sw128((uint32_t)( ra0       * 128 + (s * 2 + ua) * 16)));
            ldm_x4(a1, sAb + sw128((uint32_t)((ra0 + 16) * 128 + (s * 2 + ua) * 16)));
            ldm_x4(b0, sBb + sw128((uint32_t)( rb0       * 128 + (s * 2 + ub) * 16)));
            ldm_x4(b1, sBb + sw128((uint32_t)((rb0 + 16) * 128 + (s * 2 + ub) * 16)));
            mma_bf16(acc[0][0], a0, b0 + 0);
            mma_bf16(acc[0][1], a0, b0 + 2);
            mma_bf16(acc[0][2], a0, b1 + 0);
            mma_bf16(acc[0][3], a0, b1 + 2);
            mma_bf16(acc[1][0], a1, b0 + 0);
            mma_bf16(acc[1][1], a1, b0 + 2);
            mma_bf16(acc[1][2], a1, b1 + 0);
            mma_bf16(acc[1][3], a1, b1 + 2);
        }
        __syncthreads();
        p = np2; kc = nkc;
    }

    #pragma unroll
    for (int mt = 0; mt < 2; mt++) {
        #pragma unroll
        for (int nt = 0; nt < 4; nt++) {
            int r = rbase + wm * 32 + mt * 16 + (lane >> 2);
            int c = nbase + wn * 32 + nt * 8 + (lane & 3) * 2;
            float bv0 = biasp[c], bv1 = biasp[c + 1];
            float2 o0 = make_float2(acc[mt][nt][0] + bv0, acc[mt][nt][1] + bv1);
            float2 o1 = make_float2(acc[mt][nt][2] + bv0, acc[mt][nt][3] + bv1);
            *(float2*)(g_xpre + (size_t)r * NG + c)       = o0;
            *(float2*)(g_xpre + (size_t)(r + 8) * NG + c) = o1;
        }
    }
}

// ---------------- persistent recurrent layer: HMMA + flat release/acquire barrier ----------------
// 128 blocks x 512 threads (16 warps). Block bx owns n' [bx*32,+32); warp w owns k-slice
// [w*64,+64). B fragments (hi/lo) in 64 regs/thread, loaded once. Per step: warp-private
// H stage (bf16 hi/lo), ldmatrix.trans, 48 mma, frag dump, 512-thread finalize (C in regs,
// fast-math, shfl gate gather). Barrier = red.release.gpu arrive (cumulative: publishes
// all block stores ordered by the preceding __syncthreads, no MEMBAR) + ld.acquire.gpu
// poll. Output stores overlap the poll.
__global__ void __launch_bounds__(TPB) lstm_persist_kernel(int layer) {
    __shared__ __align__(16) char ssm[16 * 4096];   // 64KB: per-warp 4KB (stage A / frag dump)

    const uint32_t* Wh = layer ? g_wrh1 : g_wrh0;
    const uint32_t* Wl = layer ? g_wrl1 : g_wrl0;

    const int tid  = threadIdx.x;
    const int w    = tid >> 5, lane = tid & 31;
    const int bx   = blockIdx.x;
    const int col0 = bx * 8;
    // finalize mapping: b = w, nloc = lane (= cl*4 + g)
    const int fcl = lane >> 2, fg = lane & 3;

    // ---- preload B fragments (one-time): bh/bl[s][nt][r] ----
    uint32_t bh[4][4][2], bl[4][4][2];
    {
        int base = (bx * 16 + w) * 1024;
        #pragma unroll
        for (int s = 0; s < 4; s++)
            #pragma unroll
            for (int nt = 0; nt < 4; nt++)
                #pragma unroll
                for (int r = 0; r < 2; r++) {
                    int idx = base + s * 256 + nt * 64 + r * 32 + lane;
                    bh[s][nt][r] = Wh[idx];
                    bl[s][nt][r] = Wl[idx];
                }
    }

    const uint32_t sW  = smem_u32(ssm) + w * 4096;      // hi base; lo = +2048
    const uint32_t aoff = (uint32_t)(((lane & 7) + ((lane >> 4) << 3)) * 32 + ((lane >> 3) & 1) * 16);

    float Creg = 0.f;      // C state for (b=w, col0+fcl) — used by fg==0 threads

    for (int t = 0; t < S; t++) {
        const int cur = t & 1, nxt = cur ^ 1;

        // ---- prefetch xpre gate value (coalesced; hidden behind stage+mma) ----
        float xq = g_xpre[((size_t)t * B + w) * NG + bx * 32 + lane];

        // ---- stage this warp's H slice: 2KB hi + 2KB lo, warp-private ----
        {
            const uint4* srcH = (const uint4*)(g_hsbh[cur] + w * 1024);
            const uint4* srcL = (const uint4*)(g_hsbl[cur] + w * 1024);
            uint4* dH = (uint4*)(ssm + w * 4096);
            uint4* dL = (uint4*)(ssm + w * 4096 + 2048);
            #pragma unroll
            for (int j = 0; j < 4; j++) {
                dH[lane + j * 32] = __ldcg(srcH + lane + j * 32);
                dL[lane + j * 32] = __ldcg(srcL + lane + j * 32);
            }
        }
        __syncwarp();

        // ---- compute: 4 k16-steps x 4 n8-tiles x 3 passes ----
        float acc[4][4];
        #pragma unroll
        for (int nt = 0; nt < 4; nt++)
            #pragma unroll
            for (int q = 0; q < 4; q++) acc[nt][q] = 0.f;

        #pragma unroll
        for (int s = 0; s < 4; s++) {
            uint32_t ah[4], al[4];
            ldm_x4_t(ah, sW + s * 512 + aoff);
            ldm_x4_t(al, sW + 2048 + s * 512 + aoff);
            #pragma unroll
            for (int nt = 0; nt < 4; nt++) {
                mma_bf16(acc[nt], ah, bh[s][nt]);
                mma_bf16(acc[nt], al, bh[s][nt]);
                mma_bf16(acc[nt], ah, bl[s][nt]);
            }
        }
        __syncwarp();

        // ---- dump fragments into warp-private region (rb[b*36 + nloc]) ----
        {
            float* rb = (float*)(ssm + w * 4096);
            int m0 = lane >> 2, n0 = (lane & 3) * 2;
            #pragma unroll
            for (int nt = 0; nt < 4; nt++) {
                *(float2*)(rb + m0 * 36 + nt * 8 + n0)       = make_float2(acc[nt][0], acc[nt][1]);
                *(float2*)(rb + (m0 + 8) * 36 + nt * 8 + n0) = make_float2(acc[nt][2], acc[nt][3]);
            }
        }
        __syncthreads();

        // ---- reduce + finalize: ALL 512 threads, one per (b=w, nloc=lane) ----
        float v = xq;
        #pragma unroll
        for (int ww = 0; ww < 16; ww++)
            v += ((const float*)(ssm + ww * 4096))[w * 36 + lane];

        // unified activation: sigmoid for gates i/f/o, tanh for g
        float aC = (fg == 2) ? 2.f : 1.f;
        float bC = (fg == 2) ? -2.f : -1.f;
        float cC = (fg == 2) ? -1.f : 0.f;
        float act = __fdividef(aC, 1.f + __expf(bC * v)) + cC;

        int lb = lane & ~3;
        float aI = __shfl_sync(0xffffffffu, act, lb + 0);
        float aF = __shfl_sync(0xffffffffu, act, lb + 1);
        float aG = __shfl_sync(0xffffffffu, act, lb + 2);
        float aO = __shfl_sync(0xffffffffu, act, lb + 3);

        float Hval = 0.f;
        __nv_bfloat16 hHi, hLo;
        if (fg == 0) {
            float C = aF * Creg + aI * aG;
            Creg = C;
            float tC = __fdividef(2.f, 1.f + __expf(-2.f * C)) - 1.f;
            Hval = aO * tC;
            int col = col0 + fcl;
            hHi = __float2bfloat16(Hval);
            hLo = __float2bfloat16(Hval - __bfloat162float(hHi));
            g_hsbh[nxt][col * 16 + w] = hHi;
            g_hsbl[nxt][col * 16 + w] = hLo;
        }
        __syncthreads();

        // ---- flat barrier: release-arrive; output stores overlap the acquire-poll ----
        if (tid == 0)
            red_release_add(&g_bar, 1u);
        if (fg == 0) {
            size_t off = ((size_t)t * B + w) * DH + col0 + fcl;
            if (layer == 0) { g_xh[off] = hHi; g_xl[off] = hLo; }
            else            { g_h1all[off] = Hval; }
        }
        if (tid == 0) {
            unsigned target = (unsigned)(t + 1) * NBLK;
            while (ld_acquire_gpu(&g_bar) < target) { __nanosleep(16); }
        }
        __syncthreads();
    }
}

// ---------------- FC head + 2-class log_softmax ----------------
__global__ void __launch_bounds__(256) fc_kernel(const float* __restrict__ Wfc,
                                                 const float* __restrict__ bfc,
                                                 float* __restrict__ out) {
    int tid = threadIdx.x;
    int w = tid >> 5, lane = tid & 31;
    int row = blockIdx.x * 8 + w;
    const float* h = g_h1all + (size_t)row * DH;
    float a0 = 0.f, a1 = 0.f;
    for (int k = lane; k < DH; k += 32) {
        float hv = h[k];
        a0 += hv * Wfc[k * 2 + 0];
        a1 += hv * Wfc[k * 2 + 1];
    }
    #pragma unroll
    for (int off = 16; off; off >>= 1) {
        a0 += __shfl_xor_sync(0xFFFFFFFFu, a0, off);
        a1 += __shfl_xor_sync(0xFFFFFFFFu, a1, off);
    }
    if (lane == 0) {
        float l0 = a0 + bfc[0], l1 = a1 + bfc[1];
        float m  = fmaxf(l0, l1);
        float lse = m + logf(expf(l0 - m) + expf(l1 - m));
        int t = row >> 4, b = row & 15;
        out[((size_t)b * S + t) * 2 + 0] = l0 - lse;
        out[((size_t)b * S + t) * 2 + 1] = l1 - lse;
    }
}

// ---------------- launcher (graph-capturable, allocation-free) ----------------
extern "C" void kernel_launch(void* const* d_in, const int* in_sizes, int n_in,
                              void* d_out, int out_size) {
    const int*   tokens = (const int*)d_in[0];
    const float* emb    = (const float*)d_in[1];
    WPtrs p;
    for (int g = 0; g < 4; g++) {
        p.W0[g] = (const float*)d_in[2  + g * 2];
        p.b0[g] = (const float*)d_in[3  + g * 2];
        p.W1[g] = (const float*)d_in[10 + g * 2];
        p.b1[g] = (const float*)d_in[11 + g * 2];
    }
    const float* Wfc = (const float*)d_in[18];
    const float* bfc = (const float*)d_in[19];
    float* out = (float*)d_out;

    packb_kernel<<<(NG + 255) / 256, 256>>>(p);
    packw_rec_kernel<<<WREC_SZ / 256, 256>>>(p, 0);
    packw_rec_kernel<<<WREC_SZ / 256, 256>>>(p, 1);
    packw_bf16_kernel<<<(NG * DIN + 255) / 256, 256>>>(p, 0);
    packw_bf16_kernel<<<(NG * DH  + 255) / 256, 256>>>(p, 1);

    // ----- layer 0 -----
    init_kernel<<<128, 256>>>();
    xcvt_kernel<<<(ROWS * DIN + 255) / 256, 256>>>(emb, tokens);
    mma_xpre_kernel<<<dim3(ROWS / 128, NG / 64), 256>>>(0);
    lstm_persist_kernel<<<NBLK, TPB>>>(0);   // finalize writes g_xh/g_xl for layer 1

    // ----- layer 1 -----
    init_kernel<<<128, 256>>>();
    mma_xpre_kernel<<<dim3(ROWS / 128, NG / 64), 256>>>(1);
    lstm_persist_kernel<<<NBLK, TPB>>>(1);

    // ----- head -----
    fc_kernel<<<ROWS / 8, 256>>>(Wfc, bfc, out);
}